// round 15
// baseline (speedup 1.0000x reference)
#include <cuda_runtime.h>
#include <math.h>

#define BB  16
#define CC  64
#define HH  128
#define WW  128
#define HW  (HH*WW)
#define BC  (BB*CC)

// Order-preserving encoded per-plane max (atomicMax target); memset 0 per launch.
__device__ unsigned g_enc[BC];

__device__ __forceinline__ float sigmoidf_(float v) {
    return 1.0f / (1.0f + expf(-v));
}
__device__ __forceinline__ unsigned smem_u32(const void* p) {
    return (unsigned)__cvta_generic_to_shared(p);
}
__device__ __forceinline__ unsigned enc_f(float f) {
    unsigned u = __float_as_uint(f);
    return (u & 0x80000000u) ? ~u : (u | 0x80000000u);
}
__device__ __forceinline__ float dec_f(unsigned k) {
    unsigned u = (k & 0x80000000u) ? (k & 0x7FFFFFFFu) : ~k;
    return __uint_as_float(u);
}
// T = logit(sigmoid(v) - 0.01), double precision (matches previous rounds bitwise path)
__device__ __forceinline__ float thresh_from_max(float v) {
    float ps = sigmoidf_(v);
    float M  = ps - 0.01f;
    if (M > 0.0f) {
        double dM = (double)M;
        return (float)log(dM / (1.0 - dM));
    }
    return -INFINITY;
}

// ---------------------------------------------------------------------------
// K1a: plane max, 4 segment-blocks per plane, atomicMax on encoded key.
// ---------------------------------------------------------------------------
__global__ __launch_bounds__(256) void k1a_max(const float* __restrict__ x)
{
    const int bc  = blockIdx.x >> 2;
    const int seg = blockIdx.x & 3;
    const int t   = threadIdx.x;
    const float4* xp = (const float4*)(x + (size_t)bc * HW) + seg * 1024;

    float mx = -INFINITY;
    #pragma unroll
    for (int j = 0; j < 4; ++j) {
        float4 v = __ldg(xp + j * 256 + t);
        mx = fmaxf(fmaxf(fmaxf(mx, v.x), fmaxf(v.y, v.z)), v.w);
    }
    #pragma unroll
    for (int o = 16; o; o >>= 1) mx = fmaxf(mx, __shfl_xor_sync(0xffffffffu, mx, o));
    __shared__ float red[8];
    if ((t & 31) == 0) red[t >> 5] = mx;
    __syncthreads();
    if (t == 0) {
        float v = red[0];
        #pragma unroll
        for (int k = 1; k < 8; ++k) v = fmaxf(v, red[k]);
        atomicMax(&g_enc[bc], enc_f(v));
    }
}

// ---------------------------------------------------------------------------
// FAT kernel, 640 blocks x 512 threads:
//   blocks [0,128):    k2 fused conv/argmax (round-14 winner, T from g_enc)
//   blocks [128,640):  bbox masked-sum blocks (2 planes each, one per half).
// k2 blocks use the whole register file (1/SM) -> bbox blocks run ONLY on the
// 20 SMs the 128-block k2 grid leaves idle; zero interference.
// ---------------------------------------------------------------------------
#define RG2 16
#define TR2 26
#define TP  144
#define TSZ2 (TR2 * TP)
#define NCHUNK 832
#define CPH 32
#define NBUF 3
#define NK2 128

#define SM_TILES  (2 * NBUF * TSZ2)
#define SM_SCW    (SM_TILES)
#define SM_SCH    (SM_SCW + CC * 11)
#define SM_SSW    (SM_SCH + CC * 11)
#define SM_SSH    (SM_SSW + CC)
#define SM_STV    (SM_SSH + CC)
#define SM_FLOATS (SM_STV + CC)

__global__ __launch_bounds__(512, 1) void k_fat(
    const float* __restrict__ x,
    const float* __restrict__ w_bbx,
    const float* __restrict__ w_width,
    const float* __restrict__ w_width_sh,
    const float* __restrict__ w_height,
    const float* __restrict__ w_height_sh,
    float* __restrict__ out)
{
    extern __shared__ float sm[];
    const int t = threadIdx.x;

    // ======================= bbox blocks ====================================
    if (blockIdx.x >= NK2) {
        const int half = t >> 8;            // 0/1
        const int ht   = t & 255;
        const int bc   = ((int)blockIdx.x - NK2) * 2 + half;
        const int c    = bc % CC;
        const int b    = bc / CC;
        const float* __restrict__ xp = x + (size_t)bc * HW;

        const float vmax = dec_f(g_enc[bc]);
        const float T    = thresh_from_max(vmax);

        float cw[11], ch[11];
        #pragma unroll
        for (int k = 0; k < 11; ++k) { cw[k] = w_width[c*11+k]; ch[k] = w_height[c*11+k]; }
        const float s0 = w_bbx[c] * 128.0f;
        const float sW = s0 * w_width_sh[c];
        const float sH = s0 * w_height_sh[c];

        float S = 0.f, Sc = 0.f, Sr = 0.f, Sw = 0.f, Sh = 0.f;
        #pragma unroll
        for (int j = 0; j < 16; ++j) {
            const int i0 = 1024 * j + 4 * ht;
            float4 v4 = __ldg((const float4*)(xp + i0));
            float vv[4] = {v4.x, v4.y, v4.z, v4.w};
            if (vv[0] > T || vv[1] > T || vv[2] > T || vv[3] > T) {
                #pragma unroll
                for (int u = 0; u < 4; ++u) {
                    float v = vv[u];
                    if (v > T) {
                        int i = i0 + u;
                        int row = i >> 7, col = i & 127;
                        S  += v;
                        Sc += (float)col * v;
                        Sr += (float)row * v;
                        float wvv = 0.f;
                        #pragma unroll
                        for (int k = 0; k < 11; ++k) {
                            int cc2 = col - 5 + k;
                            if (cc2 >= 0 && cc2 < WW) wvv = fmaf(xp[(row << 7) + cc2], cw[k], wvv);
                        }
                        float hvv = 0.f;
                        #pragma unroll
                        for (int k = 0; k < 11; ++k) {
                            int rr = row - 5 + k;
                            if (rr >= 0 && rr < HH) hvv = fmaf(xp[(rr << 7) + col], ch[k], hvv);
                        }
                        Sw += wvv * sW * v;
                        Sh += hvv * sH * v;
                    }
                }
            }
        }
        #pragma unroll
        for (int o = 16; o; o >>= 1) {
            S  += __shfl_xor_sync(0xffffffffu, S,  o);
            Sc += __shfl_xor_sync(0xffffffffu, Sc, o);
            Sr += __shfl_xor_sync(0xffffffffu, Sr, o);
            Sw += __shfl_xor_sync(0xffffffffu, Sw, o);
            Sh += __shfl_xor_sync(0xffffffffu, Sh, o);
        }
        float* racc = sm + half * 40;       // [5][8] per half
        if ((ht & 31) == 0) {
            int w5 = ht >> 5;
            racc[0*8+w5] = S; racc[1*8+w5] = Sc; racc[2*8+w5] = Sr;
            racc[3*8+w5] = Sw; racc[4*8+w5] = Sh;
        }
        __syncthreads();
        if (ht == 0) {
            float a0=0,a1=0,a2=0,a3=0,a4=0;
            #pragma unroll
            for (int k = 0; k < 8; ++k) {
                a0+=racc[0*8+k]; a1+=racc[1*8+k]; a2+=racc[2*8+k];
                a3+=racc[3*8+k]; a4+=racc[4*8+k];
            }
            float ws = a3 / a0, hs = a4 / a0;
            float x1 = a1 / a0 - ws * 0.5f;
            float y1 = a2 / a0 - hs * 0.5f;
            float* bb = out + (size_t)BB * 3 * CC * HW + (size_t)bc * 6;
            bb[0] = (float)b; bb[1] = x1; bb[2] = y1;
            bb[3] = x1 + ws;  bb[4] = y1 + hs; bb[5] = sigmoidf_(vmax);
        }
        return;
    }

    // ======================= k2 blocks (round-14 winner) ====================
    float* tiles = sm;
    float* scw   = sm + SM_SCW;
    float* sch   = sm + SM_SCH;
    float* ssW   = sm + SM_SSW;
    float* ssH   = sm + SM_SSH;
    float* sTv   = sm + SM_STV;

    const int half  = t >> 8;
    const int ht    = t & 255;
    const int hwarp = ht >> 5;
    const int c4    = (t & 31) << 2;
    const int b     = blockIdx.x >> 3;       // 0..15
    const int row0  = (blockIdx.x & 7) * RG2;
    const int gr0   = row0 + 2 * hwarp;
    const int tr0   = 2 * hwarp;
    const int cbase = half * CPH;

    float* mytile = tiles + half * NBUF * TSZ2;

    for (int i = t; i < 2 * NBUF * TSZ2; i += 512) {
        int col = (i % TSZ2) % TP;
        if (col < 8 || col >= 136) tiles[i] = 0.f;
    }
    for (int i = t; i < CC * 11; i += 512) { scw[i] = w_width[i]; sch[i] = w_height[i]; }
    if (t < CC) {
        float s0 = w_bbx[t] * 128.0f;
        ssW[t] = s0 * w_width_sh[t];
        ssH[t] = s0 * w_height_sh[t];
        sTv[t] = thresh_from_max(dec_f(g_enc[b * CC + t]));
    }

    int  fdst[4], fsrc[4], fsz[4];
    bool fgo[4];
    #pragma unroll
    for (int j = 0; j < 4; ++j) {
        int chunk = ht + j * 256;
        fgo[j] = (chunk < NCHUNK);
        int rw  = chunk >> 5;
        int cc_ = (chunk & 31) << 2;
        int gr  = row0 - 5 + rw;
        bool ok = (gr >= 0 && gr < HH);
        int grc = ok ? gr : 0;
        fdst[j] = rw * TP + 8 + cc_;
        fsrc[j] = (grc << 7) + cc_;
        fsz[j]  = ok ? 16 : 0;
    }

    const float* xp0 = x + (size_t)(b * CC + cbase) * HW;

    #pragma unroll
    for (int p = 0; p < 2; ++p) {
        const float* xp = xp0 + (size_t)p * HW;
        float* tn = mytile + p * TSZ2;
        #pragma unroll
        for (int j = 0; j < 4; ++j) {
            if (fgo[j]) {
                unsigned d = smem_u32(tn + fdst[j]);
                asm volatile("cp.async.cg.shared.global [%0], [%1], 16, %2;"
                             :: "r"(d), "l"(xp + fsrc[j]), "r"(fsz[j]));
            }
        }
        asm volatile("cp.async.commit_group;");
    }

    float mS[2][4], mW[2][4], mH[2][4];
    int   iS[2][4], iW[2][4], iH[2][4];
    #pragma unroll
    for (int j = 0; j < 2; ++j)
        #pragma unroll
        for (int q = 0; q < 4; ++q) {
            mS[j][q] = -INFINITY; mW[j][q] = -INFINITY; mH[j][q] = -INFINITY;
            iS[j][q] = cbase; iW[j][q] = cbase; iH[j][q] = cbase;
        }

    const size_t ob = (size_t)(b * 3 * CC) * HW + ((size_t)gr0 << 7) + c4;
    float* oS = out + ob;
    float* oW = oS + (size_t)CC * HW;
    float* oH = oS + (size_t)2 * CC * HW;
    const float4 z4 = make_float4(0.f, 0.f, 0.f, 0.f);

    int slot = 0;
    for (int i = 0; i < CPH; ++i) {
        const int c = cbase + i;

        asm volatile("cp.async.wait_group 1;");
        __syncthreads();

        {
            const float* xp = xp0 + (size_t)(i + 2) * HW;
            float* tn = mytile + ((slot + 2) % NBUF) * TSZ2;
            if (i + 2 < CPH) {
                #pragma unroll
                for (int j = 0; j < 4; ++j) {
                    if (fgo[j]) {
                        unsigned d = smem_u32(tn + fdst[j]);
                        asm volatile("cp.async.cg.shared.global [%0], [%1], 16, %2;"
                                     :: "r"(d), "l"(xp + fsrc[j]), "r"(fsz[j]));
                    }
                }
            }
            asm volatile("cp.async.commit_group;");
        }

        const float* tl = mytile + slot * TSZ2;

        {
            const size_t off = (size_t)c * HW;
            __stcs((float4*)(oS + off), z4);
            __stcs((float4*)(oS + off + WW), z4);
            __stcs((float4*)(oW + off), z4);
            __stcs((float4*)(oW + off + WW), z4);
            __stcs((float4*)(oH + off), z4);
            __stcs((float4*)(oH + off + WW), z4);
        }

        float a0[4] = {0.f,0.f,0.f,0.f}, a1[4] = {0.f,0.f,0.f,0.f};
        {
            const float* chv = &sch[c * 11];
            #pragma unroll
            for (int k = 0; k < 12; ++k) {
                float4 v = *(const float4*)(&tl[(tr0 + k) * TP + 8 + c4]);
                if (k <= 10) {
                    float ck = chv[k];
                    a0[0] = fmaf(v.x, ck, a0[0]);
                    a0[1] = fmaf(v.y, ck, a0[1]);
                    a0[2] = fmaf(v.z, ck, a0[2]);
                    a0[3] = fmaf(v.w, ck, a0[3]);
                }
                if (k >= 1) {
                    float ck = chv[k - 1];
                    a1[0] = fmaf(v.x, ck, a1[0]);
                    a1[1] = fmaf(v.y, ck, a1[1]);
                    a1[2] = fmaf(v.z, ck, a1[2]);
                    a1[3] = fmaf(v.w, ck, a1[3]);
                }
            }
        }

        const float sWc = ssW[c], sHc = ssH[c], Tc = sTv[c];
        #pragma unroll
        for (int j = 0; j < 2; ++j) {
            float in[20];
            {
                const float* hrow = &tl[(tr0 + j + 5) * TP + c4];
                #pragma unroll
                for (int m = 0; m < 5; ++m) {
                    float4 v = *(const float4*)(hrow + 4 * m);
                    in[4*m+0] = v.x; in[4*m+1] = v.y; in[4*m+2] = v.z; in[4*m+3] = v.w;
                }
            }
            float wv[4] = {0.f,0.f,0.f,0.f};
            #pragma unroll
            for (int k = 0; k < 11; ++k) {
                float ck = scw[c * 11 + k];
                wv[0] = fmaf(in[3 + k], ck, wv[0]);
                wv[1] = fmaf(in[4 + k], ck, wv[1]);
                wv[2] = fmaf(in[5 + k], ck, wv[2]);
                wv[3] = fmaf(in[6 + k], ck, wv[3]);
            }
            const float* av = j ? a1 : a0;
            #pragma unroll
            for (int q = 0; q < 4; ++q) {
                float w_ = wv[q] * sWc;
                float h_ = av[q] * sHc;
                float xv = in[8 + q];
                float s_ = (xv > Tc) ? xv : 0.f;
                if (s_ > mS[j][q]) { mS[j][q] = s_; iS[j][q] = c; }
                if (w_ > mW[j][q]) { mW[j][q] = w_; iW[j][q] = c; }
                if (h_ > mH[j][q]) { mH[j][q] = h_; iH[j][q] = c; }
            }
        }

        slot = (slot + 1) % NBUF;
    }
    __syncthreads();

    // merge halves via smem (tiles region is dead)
    float* mb = tiles + ht * 48;
    if (half == 1) {
        #pragma unroll
        for (int j = 0; j < 2; ++j)
            #pragma unroll
            for (int q = 0; q < 4; ++q) {
                int o = (j * 4 + q) * 6;
                mb[o+0] = mS[j][q]; mb[o+1] = __int_as_float(iS[j][q]);
                mb[o+2] = mW[j][q]; mb[o+3] = __int_as_float(iW[j][q]);
                mb[o+4] = mH[j][q]; mb[o+5] = __int_as_float(iH[j][q]);
            }
    }
    __syncthreads();
    if (half == 0) {
        #pragma unroll
        for (int j = 0; j < 2; ++j)
            #pragma unroll
            for (int q = 0; q < 4; ++q) {
                int o = (j * 4 + q) * 6;
                float bv;
                bv = mb[o+0]; if (bv > mS[j][q]) { mS[j][q] = bv; iS[j][q] = __float_as_int(mb[o+1]); }
                bv = mb[o+2]; if (bv > mW[j][q]) { mW[j][q] = bv; iW[j][q] = __float_as_int(mb[o+3]); }
                bv = mb[o+4]; if (bv > mH[j][q]) { mH[j][q] = bv; iH[j][q] = __float_as_int(mb[o+5]); }
                mb[o+0] = mS[j][q]; mb[o+1] = __int_as_float(iS[j][q]);
                mb[o+2] = mW[j][q]; mb[o+3] = __int_as_float(iW[j][q]);
                mb[o+4] = mH[j][q]; mb[o+5] = __int_as_float(iH[j][q]);
            }
    }
    __syncthreads();
    #pragma unroll
    for (int j = 0; j < 2; ++j)
        #pragma unroll
        for (int q = 0; q < 4; ++q) {
            int o = (j * 4 + q) * 6;
            mS[j][q] = mb[o+0]; iS[j][q] = __float_as_int(mb[o+1]);
            mW[j][q] = mb[o+2]; iW[j][q] = __float_as_int(mb[o+3]);
            mH[j][q] = mb[o+4]; iH[j][q] = __float_as_int(mb[o+5]);
        }

    // scatter own channel range (zeros already written in-loop)
    #pragma unroll
    for (int j = 0; j < 2; ++j)
        #pragma unroll
        for (int q = 0; q < 4; ++q) {
            if (iS[j][q] >= cbase && iS[j][q] < cbase + CPH)
                oS[(size_t)iS[j][q] * HW + j * WW + q] = mS[j][q];
            if (iW[j][q] >= cbase && iW[j][q] < cbase + CPH)
                oW[(size_t)iW[j][q] * HW + j * WW + q] = mW[j][q];
            if (iH[j][q] >= cbase && iH[j][q] < cbase + CPH)
                oH[(size_t)iH[j][q] * HW + j * WW + q] = mH[j][q];
        }
}

extern "C" void kernel_launch(void* const* d_in, const int* in_sizes, int n_in,
                              void* d_out, int out_size)
{
    const float* x           = (const float*)d_in[0];
    const float* w_bbx       = (const float*)d_in[1];
    const float* w_width     = (const float*)d_in[2];
    const float* w_width_sh  = (const float*)d_in[3];
    const float* w_height    = (const float*)d_in[4];
    const float* w_height_sh = (const float*)d_in[5];
    float* out = (float*)d_out;

    void* enc_addr = nullptr;
    cudaGetSymbolAddress(&enc_addr, g_enc);
    cudaMemsetAsync(enc_addr, 0, BC * sizeof(unsigned));

    k1a_max<<<BC * 4, 256>>>(x);

    const int smem_bytes = SM_FLOATS * (int)sizeof(float);
    cudaFuncSetAttribute(k_fat, cudaFuncAttributeMaxDynamicSharedMemorySize, smem_bytes);
    k_fat<<<NK2 + BC / 2, 512, smem_bytes>>>(x, w_bbx, w_width, w_width_sh,
                                             w_height, w_height_sh, out);
}

// round 16
// speedup vs baseline: 1.3698x; 1.3698x over previous
#include <cuda_runtime.h>
#include <math.h>

#define BB  16
#define CC  64
#define HH  128
#define WW  128
#define HW  (HH*WW)
#define BC  (BB*CC)

// Per-(b,c) x-space threshold T = logit(sigmoid(max x) - 0.01), from k1.
__device__ float g_T[BC];

__device__ __forceinline__ float sigmoidf_(float v) {
    return 1.0f / (1.0f + expf(-v));
}
__device__ __forceinline__ unsigned smem_u32(const void* p) {
    return (unsigned)__cvta_generic_to_shared(p);
}

// ---------------------------------------------------------------------------
// K1: per-(b,c) plane cached in 64KB smem -> x read from DRAM exactly once.
// pass 1: gmem->smem + max; pass 2: masked sums entirely from smem.
// ---------------------------------------------------------------------------
__global__ __launch_bounds__(256) void k1_stats(
    const float* __restrict__ x,
    const float* __restrict__ w_bbx,
    const float* __restrict__ w_width,
    const float* __restrict__ w_width_sh,
    const float* __restrict__ w_height,
    const float* __restrict__ w_height_sh,
    float* __restrict__ out)
{
    extern __shared__ float xs[];   // HW floats = 64 KB
    const int bc = blockIdx.x;
    const int b  = bc / CC;
    const int c  = bc % CC;
    const float* __restrict__ xp = x + (size_t)bc * HW;
    const int t = threadIdx.x;

    // pass 1: stream plane to smem, track max (float4, MLP=16)
    float mx = -INFINITY;
    #pragma unroll
    for (int j = 0; j < 16; ++j) {
        const int i0 = 1024 * j + 4 * t;
        float4 v = __ldg((const float4*)(xp + i0));
        *(float4*)(xs + i0) = v;
        mx = fmaxf(fmaxf(fmaxf(mx, v.x), fmaxf(v.y, v.z)), v.w);
    }
    __shared__ float red[8];
    #pragma unroll
    for (int o = 16; o; o >>= 1) mx = fmaxf(mx, __shfl_xor_sync(0xffffffffu, mx, o));
    if ((t & 31) == 0) red[t >> 5] = mx;
    __syncthreads();
    __shared__ float sT, sps;
    if (t == 0) {
        float v = red[0];
        #pragma unroll
        for (int k = 1; k < 8; ++k) v = fmaxf(v, red[k]);
        float ps = sigmoidf_(v);
        float M  = ps - 0.01f;
        float T;
        if (M > 0.0f) {
            double dM = (double)M;
            T = (float)log(dM / (1.0 - dM));
        } else {
            T = -INFINITY;
        }
        sT = T; sps = ps;
        g_T[bc] = T;
    }
    __syncthreads();
    const float T = sT;

    float cw[11], ch[11];
    #pragma unroll
    for (int k = 0; k < 11; ++k) { cw[k] = w_width[c*11+k]; ch[k] = w_height[c*11+k]; }
    const float s0 = w_bbx[c] * 128.0f;
    const float sW = s0 * w_width_sh[c];
    const float sH = s0 * w_height_sh[c];

    // pass 2: masked sums, all reads from smem
    float S = 0.f, Sc = 0.f, Sr = 0.f, Sw = 0.f, Sh = 0.f;
    #pragma unroll
    for (int j = 0; j < 16; ++j) {
        const int i0 = 1024 * j + 4 * t;
        float4 v4 = *(const float4*)(xs + i0);
        float vv[4] = {v4.x, v4.y, v4.z, v4.w};
        if (vv[0] > T || vv[1] > T || vv[2] > T || vv[3] > T) {
            #pragma unroll
            for (int u = 0; u < 4; ++u) {
                float v = vv[u];
                if (v > T) {
                    int i = i0 + u;
                    int row = i >> 7, col = i & 127;
                    S  += v;
                    Sc += (float)col * v;
                    Sr += (float)row * v;
                    float wvv = 0.f;
                    #pragma unroll
                    for (int k = 0; k < 11; ++k) {
                        int cc2 = col - 5 + k;
                        if (cc2 >= 0 && cc2 < WW) wvv = fmaf(xs[(row << 7) + cc2], cw[k], wvv);
                    }
                    float hvv = 0.f;
                    #pragma unroll
                    for (int k = 0; k < 11; ++k) {
                        int rr = row - 5 + k;
                        if (rr >= 0 && rr < HH) hvv = fmaf(xs[(rr << 7) + col], ch[k], hvv);
                    }
                    Sw += wvv * sW * v;
                    Sh += hvv * sH * v;
                }
            }
        }
    }
    __shared__ float racc[5][8];
    #pragma unroll
    for (int o = 16; o; o >>= 1) {
        S  += __shfl_xor_sync(0xffffffffu, S,  o);
        Sc += __shfl_xor_sync(0xffffffffu, Sc, o);
        Sr += __shfl_xor_sync(0xffffffffu, Sr, o);
        Sw += __shfl_xor_sync(0xffffffffu, Sw, o);
        Sh += __shfl_xor_sync(0xffffffffu, Sh, o);
    }
    if ((t & 31) == 0) {
        int w5 = t >> 5;
        racc[0][w5] = S; racc[1][w5] = Sc; racc[2][w5] = Sr; racc[3][w5] = Sw; racc[4][w5] = Sh;
    }
    __syncthreads();
    if (t == 0) {
        float a0=0,a1=0,a2=0,a3=0,a4=0;
        #pragma unroll
        for (int k = 0; k < 8; ++k) { a0+=racc[0][k]; a1+=racc[1][k]; a2+=racc[2][k]; a3+=racc[3][k]; a4+=racc[4][k]; }
        float ws = a3 / a0, hs = a4 / a0;
        float x1 = a1 / a0 - ws * 0.5f;
        float y1 = a2 / a0 - hs * 0.5f;
        float* bb = out + (size_t)BB * 3 * CC * HW + (size_t)bc * 6;
        bb[0] = (float)b; bb[1] = x1; bb[2] = y1;
        bb[3] = x1 + ws;  bb[4] = y1 + hs; bb[5] = sps;
    }
}

// ---------------------------------------------------------------------------
// K2 (round-14 winner, unchanged): two 256-thread halves over the SAME 16
// rows; half h sweeps channels [32h,32h+32) on a 3-buffer cp.async ring;
// zero-blast interleaved into the channel loop; merge + scatter epilogue.
// ---------------------------------------------------------------------------
#define RG2 16
#define TR2 26
#define TP  144
#define TSZ2 (TR2 * TP)
#define NCHUNK 832
#define CPH 32
#define NBUF 3

#define SM_TILES  (2 * NBUF * TSZ2)
#define SM_SCW    (SM_TILES)
#define SM_SCH    (SM_SCW + CC * 11)
#define SM_SSW    (SM_SCH + CC * 11)
#define SM_SSH    (SM_SSW + CC)
#define SM_STV    (SM_SSH + CC)
#define SM_FLOATS (SM_STV + CC)

__global__ __launch_bounds__(512, 1) void k2_fused(
    const float* __restrict__ x,
    const float* __restrict__ w_bbx,
    const float* __restrict__ w_width,
    const float* __restrict__ w_width_sh,
    const float* __restrict__ w_height,
    const float* __restrict__ w_height_sh,
    float* __restrict__ out)
{
    extern __shared__ float sm[];
    float* tiles = sm;
    float* scw   = sm + SM_SCW;
    float* sch   = sm + SM_SCH;
    float* ssW   = sm + SM_SSW;
    float* ssH   = sm + SM_SSH;
    float* sTv   = sm + SM_STV;

    const int t     = threadIdx.x;
    const int half  = t >> 8;
    const int ht    = t & 255;
    const int hwarp = ht >> 5;
    const int c4    = (t & 31) << 2;
    const int b     = blockIdx.y;
    const int row0  = blockIdx.x * RG2;
    const int gr0   = row0 + 2 * hwarp;
    const int tr0   = 2 * hwarp;
    const int cbase = half * CPH;

    float* mytile = tiles + half * NBUF * TSZ2;

    for (int i = t; i < 2 * NBUF * TSZ2; i += 512) {
        int col = (i % TSZ2) % TP;
        if (col < 8 || col >= 136) tiles[i] = 0.f;
    }
    for (int i = t; i < CC * 11; i += 512) { scw[i] = w_width[i]; sch[i] = w_height[i]; }
    if (t < CC) {
        float s0 = w_bbx[t] * 128.0f;
        ssW[t] = s0 * w_width_sh[t];
        ssH[t] = s0 * w_height_sh[t];
        sTv[t] = g_T[b * CC + t];
    }

    int  fdst[4], fsrc[4], fsz[4];
    bool fgo[4];
    #pragma unroll
    for (int j = 0; j < 4; ++j) {
        int chunk = ht + j * 256;
        fgo[j] = (chunk < NCHUNK);
        int rw  = chunk >> 5;
        int cc_ = (chunk & 31) << 2;
        int gr  = row0 - 5 + rw;
        bool ok = (gr >= 0 && gr < HH);
        int grc = ok ? gr : 0;
        fdst[j] = rw * TP + 8 + cc_;
        fsrc[j] = (grc << 7) + cc_;
        fsz[j]  = ok ? 16 : 0;
    }

    const float* xp0 = x + (size_t)(b * CC + cbase) * HW;

    #pragma unroll
    for (int p = 0; p < 2; ++p) {
        const float* xp = xp0 + (size_t)p * HW;
        float* tn = mytile + p * TSZ2;
        #pragma unroll
        for (int j = 0; j < 4; ++j) {
            if (fgo[j]) {
                unsigned d = smem_u32(tn + fdst[j]);
                asm volatile("cp.async.cg.shared.global [%0], [%1], 16, %2;"
                             :: "r"(d), "l"(xp + fsrc[j]), "r"(fsz[j]));
            }
        }
        asm volatile("cp.async.commit_group;");
    }

    float mS[2][4], mW[2][4], mH[2][4];
    int   iS[2][4], iW[2][4], iH[2][4];
    #pragma unroll
    for (int j = 0; j < 2; ++j)
        #pragma unroll
        for (int q = 0; q < 4; ++q) {
            mS[j][q] = -INFINITY; mW[j][q] = -INFINITY; mH[j][q] = -INFINITY;
            iS[j][q] = cbase; iW[j][q] = cbase; iH[j][q] = cbase;
        }

    const size_t ob = (size_t)(b * 3 * CC) * HW + ((size_t)gr0 << 7) + c4;
    float* oS = out + ob;
    float* oW = oS + (size_t)CC * HW;
    float* oH = oS + (size_t)2 * CC * HW;
    const float4 z4 = make_float4(0.f, 0.f, 0.f, 0.f);

    int slot = 0;
    for (int i = 0; i < CPH; ++i) {
        const int c = cbase + i;

        asm volatile("cp.async.wait_group 1;");
        __syncthreads();

        {
            const float* xp = xp0 + (size_t)(i + 2) * HW;
            float* tn = mytile + ((slot + 2) % NBUF) * TSZ2;
            if (i + 2 < CPH) {
                #pragma unroll
                for (int j = 0; j < 4; ++j) {
                    if (fgo[j]) {
                        unsigned d = smem_u32(tn + fdst[j]);
                        asm volatile("cp.async.cg.shared.global [%0], [%1], 16, %2;"
                                     :: "r"(d), "l"(xp + fsrc[j]), "r"(fsz[j]));
                    }
                }
            }
            asm volatile("cp.async.commit_group;");
        }

        const float* tl = mytile + slot * TSZ2;

        {
            const size_t off = (size_t)c * HW;
            __stcs((float4*)(oS + off), z4);
            __stcs((float4*)(oS + off + WW), z4);
            __stcs((float4*)(oW + off), z4);
            __stcs((float4*)(oW + off + WW), z4);
            __stcs((float4*)(oH + off), z4);
            __stcs((float4*)(oH + off + WW), z4);
        }

        float a0[4] = {0.f,0.f,0.f,0.f}, a1[4] = {0.f,0.f,0.f,0.f};
        {
            const float* chv = &sch[c * 11];
            #pragma unroll
            for (int k = 0; k < 12; ++k) {
                float4 v = *(const float4*)(&tl[(tr0 + k) * TP + 8 + c4]);
                if (k <= 10) {
                    float ck = chv[k];
                    a0[0] = fmaf(v.x, ck, a0[0]);
                    a0[1] = fmaf(v.y, ck, a0[1]);
                    a0[2] = fmaf(v.z, ck, a0[2]);
                    a0[3] = fmaf(v.w, ck, a0[3]);
                }
                if (k >= 1) {
                    float ck = chv[k - 1];
                    a1[0] = fmaf(v.x, ck, a1[0]);
                    a1[1] = fmaf(v.y, ck, a1[1]);
                    a1[2] = fmaf(v.z, ck, a1[2]);
                    a1[3] = fmaf(v.w, ck, a1[3]);
                }
            }
        }

        const float sWc = ssW[c], sHc = ssH[c], Tc = sTv[c];
        #pragma unroll
        for (int j = 0; j < 2; ++j) {
            float in[20];
            {
                const float* hrow = &tl[(tr0 + j + 5) * TP + c4];
                #pragma unroll
                for (int m = 0; m < 5; ++m) {
                    float4 v = *(const float4*)(hrow + 4 * m);
                    in[4*m+0] = v.x; in[4*m+1] = v.y; in[4*m+2] = v.z; in[4*m+3] = v.w;
                }
            }
            float wv[4] = {0.f,0.f,0.f,0.f};
            #pragma unroll
            for (int k = 0; k < 11; ++k) {
                float ck = scw[c * 11 + k];
                wv[0] = fmaf(in[3 + k], ck, wv[0]);
                wv[1] = fmaf(in[4 + k], ck, wv[1]);
                wv[2] = fmaf(in[5 + k], ck, wv[2]);
                wv[3] = fmaf(in[6 + k], ck, wv[3]);
            }
            const float* av = j ? a1 : a0;
            #pragma unroll
            for (int q = 0; q < 4; ++q) {
                float w_ = wv[q] * sWc;
                float h_ = av[q] * sHc;
                float xv = in[8 + q];
                float s_ = (xv > Tc) ? xv : 0.f;
                if (s_ > mS[j][q]) { mS[j][q] = s_; iS[j][q] = c; }
                if (w_ > mW[j][q]) { mW[j][q] = w_; iW[j][q] = c; }
                if (h_ > mH[j][q]) { mH[j][q] = h_; iH[j][q] = c; }
            }
        }

        slot = (slot + 1) % NBUF;
    }
    __syncthreads();

    float* mb = tiles + ht * 48;
    if (half == 1) {
        #pragma unroll
        for (int j = 0; j < 2; ++j)
            #pragma unroll
            for (int q = 0; q < 4; ++q) {
                int o = (j * 4 + q) * 6;
                mb[o+0] = mS[j][q]; mb[o+1] = __int_as_float(iS[j][q]);
                mb[o+2] = mW[j][q]; mb[o+3] = __int_as_float(iW[j][q]);
                mb[o+4] = mH[j][q]; mb[o+5] = __int_as_float(iH[j][q]);
            }
    }
    __syncthreads();
    if (half == 0) {
        #pragma unroll
        for (int j = 0; j < 2; ++j)
            #pragma unroll
            for (int q = 0; q < 4; ++q) {
                int o = (j * 4 + q) * 6;
                float bv;
                bv = mb[o+0]; if (bv > mS[j][q]) { mS[j][q] = bv; iS[j][q] = __float_as_int(mb[o+1]); }
                bv = mb[o+2]; if (bv > mW[j][q]) { mW[j][q] = bv; iW[j][q] = __float_as_int(mb[o+3]); }
                bv = mb[o+4]; if (bv > mH[j][q]) { mH[j][q] = bv; iH[j][q] = __float_as_int(mb[o+5]); }
                mb[o+0] = mS[j][q]; mb[o+1] = __int_as_float(iS[j][q]);
                mb[o+2] = mW[j][q]; mb[o+3] = __int_as_float(iW[j][q]);
                mb[o+4] = mH[j][q]; mb[o+5] = __int_as_float(iH[j][q]);
            }
    }
    __syncthreads();
    #pragma unroll
    for (int j = 0; j < 2; ++j)
        #pragma unroll
        for (int q = 0; q < 4; ++q) {
            int o = (j * 4 + q) * 6;
            mS[j][q] = mb[o+0]; iS[j][q] = __float_as_int(mb[o+1]);
            mW[j][q] = mb[o+2]; iW[j][q] = __float_as_int(mb[o+3]);
            mH[j][q] = mb[o+4]; iH[j][q] = __float_as_int(mb[o+5]);
        }

    #pragma unroll
    for (int j = 0; j < 2; ++j)
        #pragma unroll
        for (int q = 0; q < 4; ++q) {
            if (iS[j][q] >= cbase && iS[j][q] < cbase + CPH)
                oS[(size_t)iS[j][q] * HW + j * WW + q] = mS[j][q];
            if (iW[j][q] >= cbase && iW[j][q] < cbase + CPH)
                oW[(size_t)iW[j][q] * HW + j * WW + q] = mW[j][q];
            if (iH[j][q] >= cbase && iH[j][q] < cbase + CPH)
                oH[(size_t)iH[j][q] * HW + j * WW + q] = mH[j][q];
        }
}

extern "C" void kernel_launch(void* const* d_in, const int* in_sizes, int n_in,
                              void* d_out, int out_size)
{
    const float* x           = (const float*)d_in[0];
    const float* w_bbx       = (const float*)d_in[1];
    const float* w_width     = (const float*)d_in[2];
    const float* w_width_sh  = (const float*)d_in[3];
    const float* w_height    = (const float*)d_in[4];
    const float* w_height_sh = (const float*)d_in[5];
    float* out = (float*)d_out;

    cudaFuncSetAttribute(k1_stats, cudaFuncAttributeMaxDynamicSharedMemorySize,
                         HW * (int)sizeof(float));
    k1_stats<<<BC, 256, HW * sizeof(float)>>>(x, w_bbx, w_width, w_width_sh,
                                              w_height, w_height_sh, out);

    const int smem_bytes = SM_FLOATS * (int)sizeof(float);
    cudaFuncSetAttribute(k2_fused, cudaFuncAttributeMaxDynamicSharedMemorySize, smem_bytes);
    dim3 g2(8, BB);
    k2_fused<<<g2, 512, smem_bytes>>>(x, w_bbx, w_width, w_width_sh,
                                      w_height, w_height_sh, out);
}